// round 1
// baseline (speedup 1.0000x reference)
#include <cuda_runtime.h>
#include <math.h>

// ---------------------------------------------------------------------------
// Contextual attention module, algorithmically restructured:
//   G = bd^T fd  (per-batch 1024x1024x128 GEMM)
//   S = invnorm * 9-tap diagonal stencil of G
//   F1/F2 = flat-diagonal 3-tap fuses (with transpose sandwich)
//   A = softmax over Lb
//   V[py,px] = b_shift(py,px) @ A   (16 tap-GEMMs / batch, C x Lf, K=Lb)
//   y = 0.25 * (2x2 tap combine of V)
//   out = elu(conv3x3(elu(conv3x3(y,W1)+b1), W2)+b2)  as implicit GEMMs
// ---------------------------------------------------------------------------

#define BQ 16
#define CC 128
#define HH 64
#define WW 64
#define HD 32
#define LB 1024
#define LF 1024

#define BM 128
#define BN 128
#define BK 16

// -------- device scratch (no allocations allowed) --------
__device__ float g_fd[BQ * CC * HD * HD];        // 8 MB
__device__ float g_bd[BQ * CC * HD * HD];        // 8 MB
__device__ float g_invn[BQ * LB];
__device__ float g_bufA[(size_t)BQ * LB * LF];   // 64 MB
__device__ float g_bufB[(size_t)BQ * LB * LF];   // 64 MB
__device__ float g_V[(size_t)BQ * 16 * CC * LF]; // 134 MB
__device__ float g_y[(size_t)BQ * CC * HH * WW]; // 33.5 MB
__device__ float g_h[(size_t)BQ * CC * HH * WW]; // 33.5 MB
__device__ float g_pm[BQ * 8 * LF];
__device__ float g_ps[BQ * 8 * LF];
__device__ float g_mx[BQ * LF];
__device__ float g_rs[BQ * LF];
__device__ float g_W1t[1152 * 128];
__device__ float g_W2t[1152 * 128];

// -------- prep: downsample f,b by 2 --------
__global__ void k_down(const float* __restrict__ f, const float* __restrict__ b) {
    int i = blockIdx.x * 256 + threadIdx.x;
    if (i >= BQ * CC * HD * HD) return;
    int x = i & 31;
    int y = (i >> 5) & 31;
    int cb = i >> 10;                       // bi*CC + c
    int src = (cb * HH + 2 * y) * WW + 2 * x;
    g_fd[i] = f[src];
    g_bd[i] = b[src];
}

// -------- prep: per-position sumsq of bd, then 3x3 patch inv-norms --------
__global__ void k_norm() {
    int bi = blockIdx.x;
    int p = threadIdx.x;                    // 1024 threads
    __shared__ float sq[LB];
    const float* bd = g_bd + (size_t)bi * CC * LB;
    float s = 0.f;
    for (int c = 0; c < CC; c++) {
        float v = bd[c * LB + p];
        s += v * v;
    }
    sq[p] = s;
    __syncthreads();
    int yb = p >> 5, xb = p & 31;
    float ns = 0.f;
    #pragma unroll
    for (int dy = -1; dy <= 1; dy++)
        #pragma unroll
        for (int dx = -1; dx <= 1; dx++) {
            int y2 = yb + dy, x2 = xb + dx;
            if ((unsigned)y2 < 32u && (unsigned)x2 < 32u)
                ns += sq[(y2 << 5) + x2];
        }
    float n = sqrtf(ns);
    if (n < 1e-4f) n = 1e-4f;
    g_invn[bi * LB + p] = 1.0f / n;
}

// -------- prep: transpose W[co][ci][3][3] -> Wt[tap*128+ci][co] --------
__global__ void k_transW(const float* __restrict__ W1, const float* __restrict__ W2) {
    int i = blockIdx.x * 256 + threadIdx.x;
    if (i >= 1152 * 128) return;
    int co = i & 127;
    int k = i >> 7;
    int tap = k >> 7;
    int ci = k & 127;
    int src = (co * 128 + ci) * 9 + tap;
    g_W1t[i] = W1[src];
    g_W2t[i] = W2[src];
}

// -------- GEMM: G[pb][pf] = sum_c bd[c][pb] * fd[c][pf] (K=128) --------
__global__ __launch_bounds__(256) void k_gemmG() {
    int bi = blockIdx.z;
    int m0 = blockIdx.y * BM, n0 = blockIdx.x * BN;
    __shared__ float As[BK][BM + 4];
    __shared__ float Bs[BK][BN + 4];
    const float* Ag = g_bd + (size_t)bi * CC * LB;
    const float* Bg = g_fd + (size_t)bi * CC * LB;
    float acc[8][8] = {};
    int tid = threadIdx.x;
    int tx = tid & 15, ty = tid >> 4;
    for (int k0 = 0; k0 < CC; k0 += BK) {
        for (int idx = tid; idx < BK * BM; idx += 256) {
            int mm = idx & 127, kk = idx >> 7;
            As[kk][mm] = Ag[(k0 + kk) * LB + m0 + mm];
            Bs[kk][mm] = Bg[(k0 + kk) * LB + n0 + mm];
        }
        __syncthreads();
        #pragma unroll
        for (int kk = 0; kk < BK; kk++) {
            float av[8], bv[8];
            #pragma unroll
            for (int i = 0; i < 8; i++) av[i] = As[kk][ty * 8 + i];
            #pragma unroll
            for (int j = 0; j < 8; j++) bv[j] = Bs[kk][tx * 8 + j];
            #pragma unroll
            for (int i = 0; i < 8; i++)
                #pragma unroll
                for (int j = 0; j < 8; j++) acc[i][j] += av[i] * bv[j];
        }
        __syncthreads();
    }
    float* out = g_bufA + ((size_t)bi << 20);
    #pragma unroll
    for (int i = 0; i < 8; i++)
        #pragma unroll
        for (int j = 0; j < 8; j++)
            out[(m0 + ty * 8 + i) * LF + n0 + tx * 8 + j] = acc[i][j];
}

// -------- S = invnorm[pb] * 9-tap diag stencil of G (2D bounds) --------
__global__ void k_S() {
    int bi = blockIdx.y;
    int i = blockIdx.x * 256 + threadIdx.x;      // [0, 1M)
    int pb = i >> 10, pf = i & 1023;
    int yb = pb >> 5, xb = pb & 31, yf = pf >> 5, xf = pf & 31;
    const float* G = g_bufA + ((size_t)bi << 20);
    float s = 0.f;
    #pragma unroll
    for (int dy = -1; dy <= 1; dy++)
        #pragma unroll
        for (int dx = -1; dx <= 1; dx++) {
            int yb2 = yb + dy, xb2 = xb + dx, yf2 = yf + dy, xf2 = xf + dx;
            if ((unsigned)yb2 < 32u && (unsigned)xb2 < 32u &&
                (unsigned)yf2 < 32u && (unsigned)xf2 < 32u)
                s += G[((yb2 << 5) + xb2) * LF + (yf2 << 5) + xf2];
        }
    g_bufB[((size_t)bi << 20) + i] = s * g_invn[bi * LB + pb];
}

// -------- fuse1: F1[lb][lf] = sum_k S[lb+k][lf+k] (flat bounds) --------
__global__ void k_fuse1() {
    int bi = blockIdx.y;
    int i = blockIdx.x * 256 + threadIdx.x;
    int lb = i >> 10, lf = i & 1023;
    const float* Sm = g_bufB + ((size_t)bi << 20);
    float s = 0.f;
    #pragma unroll
    for (int k = -1; k <= 1; k++) {
        int a = lb + k, c = lf + k;
        if ((unsigned)a < 1024u && (unsigned)c < 1024u)
            s += Sm[a * LF + c];
    }
    g_bufA[((size_t)bi << 20) + i] = s;
}

// -------- fuse2: transposed flat-diag fuse, output back in original layout ----
__global__ void k_fuse2() {
    int bi = blockIdx.y;
    int i = blockIdx.x * 256 + threadIdx.x;
    int lb = i >> 10, lf = i & 1023;
    int hb = lb >> 5, wb = lb & 31, hf = lf >> 5, wf = lf & 31;
    int lbT = wb * 32 + hb;
    int lfT = wf * 32 + hf;
    const float* F1 = g_bufA + ((size_t)bi << 20);
    float s = 0.f;
    #pragma unroll
    for (int k = -1; k <= 1; k++) {
        int a = lbT + k, c = lfT + k;
        if ((unsigned)a < 1024u && (unsigned)c < 1024u) {
            int wb2 = a >> 5, hb2 = a & 31;
            int wf2 = c >> 5, hf2 = c & 31;
            s += F1[(hb2 * 32 + wb2) * LF + hf2 * 32 + wf2];
        }
    }
    g_bufB[((size_t)bi << 20) + i] = s;
}

// -------- softmax over lb (x10 scale): partials --------
__global__ void k_sm_part() {
    int bi = blockIdx.z;
    int lbc = blockIdx.y;
    int lf = blockIdx.x * 128 + threadIdx.x;
    const float* F = g_bufB + ((size_t)bi << 20);
    float m = -1e30f, s = 0.f;
    for (int l = lbc * 128; l < lbc * 128 + 128; l++) {
        float v = 10.0f * F[l * LF + lf];
        if (v > m) {
            s = s * expf(m - v) + 1.0f;
            m = v;
        } else {
            s += expf(v - m);
        }
    }
    g_pm[(bi * 8 + lbc) * LF + lf] = m;
    g_ps[(bi * 8 + lbc) * LF + lf] = s;
}

__global__ void k_sm_comb() {
    int bi = blockIdx.x;
    int lf = threadIdx.x;     // 1024 threads
    float m = -1e30f;
    for (int c = 0; c < 8; c++) {
        float v = g_pm[(bi * 8 + c) * LF + lf];
        if (v > m) m = v;
    }
    float s = 0.f;
    for (int c = 0; c < 8; c++)
        s += g_ps[(bi * 8 + c) * LF + lf] * expf(g_pm[(bi * 8 + c) * LF + lf] - m);
    g_mx[bi * LF + lf] = m;
    g_rs[bi * LF + lf] = 1.0f / s;
}

__global__ void k_sm_norm() {
    int bi = blockIdx.y;
    int i = blockIdx.x * 256 + threadIdx.x;
    int lf = i & 1023;
    float v = 10.0f * g_bufB[((size_t)bi << 20) + i];
    g_bufA[((size_t)bi << 20) + i] = expf(v - g_mx[bi * LF + lf]) * g_rs[bi * LF + lf];
}

// -------- V tap-GEMMs: V[tap][c][lf] = sum_lb b_shift[c][lb] * A[lb][lf] ------
__global__ __launch_bounds__(256) void k_gemmV(const float* __restrict__ b_in) {
    int bi = blockIdx.z;
    int tap = blockIdx.y;
    int py = tap >> 2, px = tap & 3;
    int n0 = blockIdx.x * BN;
    __shared__ float As[BK][BM + 4];
    __shared__ float Bs[BK][BN + 4];
    const float* Aatt = g_bufA + ((size_t)bi << 20);
    const float* bsrc = b_in + (size_t)bi * CC * HH * WW;
    float acc[8][8] = {};
    int tid = threadIdx.x;
    int tx = tid & 15, ty = tid >> 4;
    for (int k0 = 0; k0 < LB; k0 += BK) {
        int yb = k0 >> 5;                         // constant over the 16-chunk
        int row = 2 * yb + py - 1;
        bool rowok = (row >= 0 && row < HH);
        for (int idx = tid; idx < BK * BM; idx += 256) {
            int kk = idx & 15, mm = idx >> 4;     // kk fast -> coalesced-ish x
            int xb = (k0 & 31) + kk;
            int col = 2 * xb + px - 1;
            float v = 0.f;
            if (rowok && col >= 0 && col < WW)
                v = bsrc[(mm * HH + row) * WW + col];
            As[kk][mm] = v;
        }
        for (int idx = tid; idx < BK * BN; idx += 256) {
            int nn = idx & 127, kk = idx >> 7;
            Bs[kk][nn] = Aatt[(k0 + kk) * LF + n0 + nn];
        }
        __syncthreads();
        #pragma unroll
        for (int kk = 0; kk < BK; kk++) {
            float av[8], bv[8];
            #pragma unroll
            for (int i = 0; i < 8; i++) av[i] = As[kk][ty * 8 + i];
            #pragma unroll
            for (int j = 0; j < 8; j++) bv[j] = Bs[kk][tx * 8 + j];
            #pragma unroll
            for (int i = 0; i < 8; i++)
                #pragma unroll
                for (int j = 0; j < 8; j++) acc[i][j] += av[i] * bv[j];
        }
        __syncthreads();
    }
    float* out = g_V + ((size_t)bi * 16 + tap) * CC * LF;
    #pragma unroll
    for (int i = 0; i < 8; i++)
        #pragma unroll
        for (int j = 0; j < 8; j++)
            out[(ty * 8 + i) * LF + n0 + tx * 8 + j] = acc[i][j];
}

// -------- combine: y[c][oy][ox] = 0.25 * sum of 2x2 valid V taps --------
__global__ void k_comb() {
    int bi = blockIdx.y;
    int i = blockIdx.x * 256 + threadIdx.x;       // over CC*HH*WW = 524288
    int ox = i & 63;
    int oy = (i >> 6) & 63;
    int c = i >> 12;
    int my = oy >> 1, mx = ox >> 1;
    int yfv[2], pyv[2], xfv[2], pxv[2];
    if (oy & 1) { yfv[0] = my;  pyv[0] = 2; yfv[1] = my + 1; pyv[1] = 0; }
    else        { yfv[0] = my;  pyv[0] = 1; yfv[1] = my - 1; pyv[1] = 3; }
    if (ox & 1) { xfv[0] = mx;  pxv[0] = 2; xfv[1] = mx + 1; pxv[1] = 0; }
    else        { xfv[0] = mx;  pxv[0] = 1; xfv[1] = mx - 1; pxv[1] = 3; }
    const float* V = g_V + (size_t)bi * 16 * CC * LF;
    float s = 0.f;
    #pragma unroll
    for (int a = 0; a < 2; a++) {
        if ((unsigned)yfv[a] >= 32u) continue;
        #pragma unroll
        for (int b2 = 0; b2 < 2; b2++) {
            if ((unsigned)xfv[b2] >= 32u) continue;
            int tap = pyv[a] * 4 + pxv[b2];
            s += V[((size_t)tap * CC + c) * LF + yfv[a] * 32 + xfv[b2]];
        }
    }
    g_y[((size_t)bi * CC + c) * 4096 + oy * 64 + ox] = 0.25f * s;
}

// -------- implicit-GEMM conv3x3 + bias + ELU (K=1152 tap-major) --------
__global__ __launch_bounds__(256) void k_conv(const float* __restrict__ X,
                                              const float* __restrict__ Wt,
                                              const float* __restrict__ bias,
                                              float* __restrict__ out) {
    int bi = blockIdx.z;
    int n0 = blockIdx.x * BN;                 // 128 spatial = 2 full rows
    int y0 = n0 >> 6;
    __shared__ float As[BK][BM + 4];
    __shared__ float Bs[BK][BN + 4];
    const float* Xb = X + (size_t)bi * CC * HH * WW;
    float acc[8][8] = {};
    int tid = threadIdx.x;
    int tx = tid & 15, ty = tid >> 4;
    for (int k0 = 0; k0 < 1152; k0 += BK) {
        int tap = k0 >> 7;
        int ci0 = k0 & 127;
        int ky = tap / 3 - 1, kx = tap % 3 - 1;
        for (int idx = tid; idx < BK * BM; idx += 256) {
            int mm = idx & 127, kk = idx >> 7;
            As[kk][mm] = Wt[(k0 + kk) * 128 + mm];
        }
        for (int idx = tid; idx < BK * BN; idx += 256) {
            int nn = idx & 127, kk = idx >> 7;
            int dy = nn >> 6, x = nn & 63;
            int sy = y0 + dy + ky, sx = x + kx;
            float v = 0.f;
            if ((unsigned)sy < (unsigned)HH && (unsigned)sx < (unsigned)WW)
                v = Xb[((ci0 + kk) * HH + sy) * WW + sx];
            Bs[kk][nn] = v;
        }
        __syncthreads();
        #pragma unroll
        for (int kk = 0; kk < BK; kk++) {
            float av[8], bv[8];
            #pragma unroll
            for (int i = 0; i < 8; i++) av[i] = As[kk][ty * 8 + i];
            #pragma unroll
            for (int j = 0; j < 8; j++) bv[j] = Bs[kk][tx * 8 + j];
            #pragma unroll
            for (int i = 0; i < 8; i++)
                #pragma unroll
                for (int j = 0; j < 8; j++) acc[i][j] += av[i] * bv[j];
        }
        __syncthreads();
    }
    #pragma unroll
    for (int i = 0; i < 8; i++) {
        int co = ty * 8 + i;
        float bb = bias[co];
        #pragma unroll
        for (int j = 0; j < 8; j++) {
            float v = acc[i][j] + bb;
            v = (v > 0.f) ? v : expm1f(v);
            out[((size_t)bi * CC + co) * 4096 + n0 + tx * 8 + j] = v;
        }
    }
}

// ---------------------------------------------------------------------------
extern "C" void kernel_launch(void* const* d_in, const int* in_sizes, int n_in,
                              void* d_out, int out_size) {
    const float* f  = (const float*)d_in[0];
    const float* b  = (const float*)d_in[1];
    const float* W1 = (const float*)d_in[2];
    const float* b1 = (const float*)d_in[3];
    const float* W2 = (const float*)d_in[4];
    const float* b2 = (const float*)d_in[5];
    float* out = (float*)d_out;

    float* yptr;  cudaGetSymbolAddress((void**)&yptr, g_y);
    float* hptr;  cudaGetSymbolAddress((void**)&hptr, g_h);
    float* w1t;   cudaGetSymbolAddress((void**)&w1t, g_W1t);
    float* w2t;   cudaGetSymbolAddress((void**)&w2t, g_W2t);

    k_down<<<(BQ * CC * HD * HD + 255) / 256, 256>>>(f, b);
    k_norm<<<BQ, 1024>>>();
    k_transW<<<(1152 * 128 + 255) / 256, 256>>>(W1, W2);

    k_gemmG<<<dim3(8, 8, BQ), 256>>>();
    k_S<<<dim3(4096, BQ), 256>>>();
    k_fuse1<<<dim3(4096, BQ), 256>>>();
    k_fuse2<<<dim3(4096, BQ), 256>>>();

    k_sm_part<<<dim3(8, 8, BQ), 128>>>();
    k_sm_comb<<<BQ, 1024>>>();
    k_sm_norm<<<dim3(4096, BQ), 256>>>();

    k_gemmV<<<dim3(8, 16, BQ), 256>>>(b);
    k_comb<<<dim3(2048, BQ), 256>>>();

    k_conv<<<dim3(32, 1, BQ), 256>>>(yptr, w1t, b1, hptr);
    k_conv<<<dim3(32, 1, BQ), 256>>>(hptr, w2t, b2, out);

    (void)in_sizes; (void)n_in; (void)out_size;
}

// round 2
// speedup vs baseline: 1.0003x; 1.0003x over previous
#include <cuda_runtime.h>
#include <math.h>

// ---------------------------------------------------------------------------
// Contextual attention module, algorithmically restructured:
//   G = bd^T fd  (per-batch 1024x1024x128 GEMM)
//   S = invnorm * 9-tap diagonal stencil of G
//   F1/F2 = flat-diagonal 3-tap fuses (with transpose sandwich)
//   A = softmax over Lb
//   V[py,px] = b_shift(py,px) @ A   (16 tap-GEMMs / batch, C x Lf, K=Lb)
//   y = 0.25 * (2x2 tap combine of V)
//   out = elu(conv3x3(elu(conv3x3(y,W1)+b1), W2)+b2)  as implicit GEMMs
// ---------------------------------------------------------------------------

#define BQ 16
#define CC 128
#define HH 64
#define WW 64
#define HD 32
#define LB 1024
#define LF 1024

#define BM 128
#define BN 128
#define BK 16

// -------- device scratch (no allocations allowed) --------
__device__ float g_fd[BQ * CC * HD * HD];        // 8 MB
__device__ float g_bd[BQ * CC * HD * HD];        // 8 MB
__device__ float g_invn[BQ * LB];
__device__ float g_bufA[(size_t)BQ * LB * LF];   // 64 MB
__device__ float g_bufB[(size_t)BQ * LB * LF];   // 64 MB
__device__ float g_V[(size_t)BQ * 16 * CC * LF]; // 134 MB
__device__ float g_y[(size_t)BQ * CC * HH * WW]; // 33.5 MB
__device__ float g_h[(size_t)BQ * CC * HH * WW]; // 33.5 MB
__device__ float g_pm[BQ * 8 * LF];
__device__ float g_ps[BQ * 8 * LF];
__device__ float g_mx[BQ * LF];
__device__ float g_rs[BQ * LF];
__device__ float g_W1t[1152 * 128];
__device__ float g_W2t[1152 * 128];

// -------- prep: downsample f,b by 2 --------
__global__ void k_down(const float* __restrict__ f, const float* __restrict__ b) {
    int i = blockIdx.x * 256 + threadIdx.x;
    if (i >= BQ * CC * HD * HD) return;
    int x = i & 31;
    int y = (i >> 5) & 31;
    int cb = i >> 10;                       // bi*CC + c
    int src = (cb * HH + 2 * y) * WW + 2 * x;
    g_fd[i] = f[src];
    g_bd[i] = b[src];
}

// -------- prep: per-position sumsq of bd, then 3x3 patch inv-norms --------
__global__ void k_norm() {
    int bi = blockIdx.x;
    int p = threadIdx.x;                    // 1024 threads
    __shared__ float sq[LB];
    const float* bd = g_bd + (size_t)bi * CC * LB;
    float s = 0.f;
    for (int c = 0; c < CC; c++) {
        float v = bd[c * LB + p];
        s += v * v;
    }
    sq[p] = s;
    __syncthreads();
    int yb = p >> 5, xb = p & 31;
    float ns = 0.f;
    #pragma unroll
    for (int dy = -1; dy <= 1; dy++)
        #pragma unroll
        for (int dx = -1; dx <= 1; dx++) {
            int y2 = yb + dy, x2 = xb + dx;
            if ((unsigned)y2 < 32u && (unsigned)x2 < 32u)
                ns += sq[(y2 << 5) + x2];
        }
    float n = sqrtf(ns);
    if (n < 1e-4f) n = 1e-4f;
    g_invn[bi * LB + p] = 1.0f / n;
}

// -------- prep: transpose W[co][ci][3][3] -> Wt[tap*128+ci][co] --------
__global__ void k_transW(const float* __restrict__ W1, const float* __restrict__ W2) {
    int i = blockIdx.x * 256 + threadIdx.x;
    if (i >= 1152 * 128) return;
    int co = i & 127;
    int k = i >> 7;
    int tap = k >> 7;
    int ci = k & 127;
    int src = (co * 128 + ci) * 9 + tap;
    g_W1t[i] = W1[src];
    g_W2t[i] = W2[src];
}

// -------- GEMM: G[pb][pf] = sum_c bd[c][pb] * fd[c][pf] (K=128) --------
__global__ __launch_bounds__(256) void k_gemmG() {
    int bi = blockIdx.z;
    int m0 = blockIdx.y * BM, n0 = blockIdx.x * BN;
    __shared__ float As[BK][BM + 4];
    __shared__ float Bs[BK][BN + 4];
    const float* Ag = g_bd + (size_t)bi * CC * LB;
    const float* Bg = g_fd + (size_t)bi * CC * LB;
    float acc[8][8] = {};
    int tid = threadIdx.x;
    int tx = tid & 15, ty = tid >> 4;
    for (int k0 = 0; k0 < CC; k0 += BK) {
        for (int idx = tid; idx < BK * BM; idx += 256) {
            int mm = idx & 127, kk = idx >> 7;
            As[kk][mm] = Ag[(k0 + kk) * LB + m0 + mm];
            Bs[kk][mm] = Bg[(k0 + kk) * LB + n0 + mm];
        }
        __syncthreads();
        #pragma unroll
        for (int kk = 0; kk < BK; kk++) {
            float av[8], bv[8];
            #pragma unroll
            for (int i = 0; i < 8; i++) av[i] = As[kk][ty * 8 + i];
            #pragma unroll
            for (int j = 0; j < 8; j++) bv[j] = Bs[kk][tx * 8 + j];
            #pragma unroll
            for (int i = 0; i < 8; i++)
                #pragma unroll
                for (int j = 0; j < 8; j++) acc[i][j] += av[i] * bv[j];
        }
        __syncthreads();
    }
    float* out = g_bufA + ((size_t)bi << 20);
    #pragma unroll
    for (int i = 0; i < 8; i++)
        #pragma unroll
        for (int j = 0; j < 8; j++)
            out[(m0 + ty * 8 + i) * LF + n0 + tx * 8 + j] = acc[i][j];
}

// -------- S = invnorm[pb] * 9-tap diag stencil of G (2D bounds) --------
__global__ void k_S() {
    int bi = blockIdx.y;
    int i = blockIdx.x * 256 + threadIdx.x;      // [0, 1M)
    int pb = i >> 10, pf = i & 1023;
    int yb = pb >> 5, xb = pb & 31, yf = pf >> 5, xf = pf & 31;
    const float* G = g_bufA + ((size_t)bi << 20);
    float s = 0.f;
    #pragma unroll
    for (int dy = -1; dy <= 1; dy++)
        #pragma unroll
        for (int dx = -1; dx <= 1; dx++) {
            int yb2 = yb + dy, xb2 = xb + dx, yf2 = yf + dy, xf2 = xf + dx;
            if ((unsigned)yb2 < 32u && (unsigned)xb2 < 32u &&
                (unsigned)yf2 < 32u && (unsigned)xf2 < 32u)
                s += G[((yb2 << 5) + xb2) * LF + (yf2 << 5) + xf2];
        }
    g_bufB[((size_t)bi << 20) + i] = s * g_invn[bi * LB + pb];
}

// -------- fuse1: F1[lb][lf] = sum_k S[lb+k][lf+k] (flat bounds) --------
__global__ void k_fuse1() {
    int bi = blockIdx.y;
    int i = blockIdx.x * 256 + threadIdx.x;
    int lb = i >> 10, lf = i & 1023;
    const float* Sm = g_bufB + ((size_t)bi << 20);
    float s = 0.f;
    #pragma unroll
    for (int k = -1; k <= 1; k++) {
        int a = lb + k, c = lf + k;
        if ((unsigned)a < 1024u && (unsigned)c < 1024u)
            s += Sm[a * LF + c];
    }
    g_bufA[((size_t)bi << 20) + i] = s;
}

// -------- fuse2: transposed flat-diag fuse, output back in original layout ----
__global__ void k_fuse2() {
    int bi = blockIdx.y;
    int i = blockIdx.x * 256 + threadIdx.x;
    int lb = i >> 10, lf = i & 1023;
    int hb = lb >> 5, wb = lb & 31, hf = lf >> 5, wf = lf & 31;
    int lbT = wb * 32 + hb;
    int lfT = wf * 32 + hf;
    const float* F1 = g_bufA + ((size_t)bi << 20);
    float s = 0.f;
    #pragma unroll
    for (int k = -1; k <= 1; k++) {
        int a = lbT + k, c = lfT + k;
        if ((unsigned)a < 1024u && (unsigned)c < 1024u) {
            int wb2 = a >> 5, hb2 = a & 31;
            int wf2 = c >> 5, hf2 = c & 31;
            s += F1[(hb2 * 32 + wb2) * LF + hf2 * 32 + wf2];
        }
    }
    g_bufB[((size_t)bi << 20) + i] = s;
}

// -------- softmax over lb (x10 scale): partials --------
__global__ void k_sm_part() {
    int bi = blockIdx.z;
    int lbc = blockIdx.y;
    int lf = blockIdx.x * 128 + threadIdx.x;
    const float* F = g_bufB + ((size_t)bi << 20);
    float m = -1e30f, s = 0.f;
    for (int l = lbc * 128; l < lbc * 128 + 128; l++) {
        float v = 10.0f * F[l * LF + lf];
        if (v > m) {
            s = s * expf(m - v) + 1.0f;
            m = v;
        } else {
            s += expf(v - m);
        }
    }
    g_pm[(bi * 8 + lbc) * LF + lf] = m;
    g_ps[(bi * 8 + lbc) * LF + lf] = s;
}

__global__ void k_sm_comb() {
    int bi = blockIdx.x;
    int lf = threadIdx.x;     // 1024 threads
    float m = -1e30f;
    for (int c = 0; c < 8; c++) {
        float v = g_pm[(bi * 8 + c) * LF + lf];
        if (v > m) m = v;
    }
    float s = 0.f;
    for (int c = 0; c < 8; c++)
        s += g_ps[(bi * 8 + c) * LF + lf] * expf(g_pm[(bi * 8 + c) * LF + lf] - m);
    g_mx[bi * LF + lf] = m;
    g_rs[bi * LF + lf] = 1.0f / s;
}

__global__ void k_sm_norm() {
    int bi = blockIdx.y;
    int i = blockIdx.x * 256 + threadIdx.x;
    int lf = i & 1023;
    float v = 10.0f * g_bufB[((size_t)bi << 20) + i];
    g_bufA[((size_t)bi << 20) + i] = expf(v - g_mx[bi * LF + lf]) * g_rs[bi * LF + lf];
}

// -------- V tap-GEMMs: V[tap][c][lf] = sum_lb b_shift[c][lb] * A[lb][lf] ------
__global__ __launch_bounds__(256) void k_gemmV(const float* __restrict__ b_in) {
    int bi = blockIdx.z;
    int tap = blockIdx.y;
    int py = tap >> 2, px = tap & 3;
    int n0 = blockIdx.x * BN;
    __shared__ float As[BK][BM + 4];
    __shared__ float Bs[BK][BN + 4];
    const float* Aatt = g_bufA + ((size_t)bi << 20);
    const float* bsrc = b_in + (size_t)bi * CC * HH * WW;
    float acc[8][8] = {};
    int tid = threadIdx.x;
    int tx = tid & 15, ty = tid >> 4;
    for (int k0 = 0; k0 < LB; k0 += BK) {
        int yb = k0 >> 5;                         // constant over the 16-chunk
        int row = 2 * yb + py - 1;
        bool rowok = (row >= 0 && row < HH);
        for (int idx = tid; idx < BK * BM; idx += 256) {
            int kk = idx & 15, mm = idx >> 4;     // kk fast -> coalesced-ish x
            int xb = (k0 & 31) + kk;
            int col = 2 * xb + px - 1;
            float v = 0.f;
            if (rowok && col >= 0 && col < WW)
                v = bsrc[(mm * HH + row) * WW + col];
            As[kk][mm] = v;
        }
        for (int idx = tid; idx < BK * BN; idx += 256) {
            int nn = idx & 127, kk = idx >> 7;
            Bs[kk][nn] = Aatt[(k0 + kk) * LF + n0 + nn];
        }
        __syncthreads();
        #pragma unroll
        for (int kk = 0; kk < BK; kk++) {
            float av[8], bv[8];
            #pragma unroll
            for (int i = 0; i < 8; i++) av[i] = As[kk][ty * 8 + i];
            #pragma unroll
            for (int j = 0; j < 8; j++) bv[j] = Bs[kk][tx * 8 + j];
            #pragma unroll
            for (int i = 0; i < 8; i++)
                #pragma unroll
                for (int j = 0; j < 8; j++) acc[i][j] += av[i] * bv[j];
        }
        __syncthreads();
    }
    float* out = g_V + ((size_t)bi * 16 + tap) * CC * LF;
    #pragma unroll
    for (int i = 0; i < 8; i++)
        #pragma unroll
        for (int j = 0; j < 8; j++)
            out[(ty * 8 + i) * LF + n0 + tx * 8 + j] = acc[i][j];
}

// -------- combine: y[c][oy][ox] = 0.25 * sum of 2x2 valid V taps --------
__global__ void k_comb() {
    int bi = blockIdx.y;
    int i = blockIdx.x * 256 + threadIdx.x;       // over CC*HH*WW = 524288
    int ox = i & 63;
    int oy = (i >> 6) & 63;
    int c = i >> 12;
    int my = oy >> 1, mx = ox >> 1;
    int yfv[2], pyv[2], xfv[2], pxv[2];
    if (oy & 1) { yfv[0] = my;  pyv[0] = 2; yfv[1] = my + 1; pyv[1] = 0; }
    else        { yfv[0] = my;  pyv[0] = 1; yfv[1] = my - 1; pyv[1] = 3; }
    if (ox & 1) { xfv[0] = mx;  pxv[0] = 2; xfv[1] = mx + 1; pxv[1] = 0; }
    else        { xfv[0] = mx;  pxv[0] = 1; xfv[1] = mx - 1; pxv[1] = 3; }
    const float* V = g_V + (size_t)bi * 16 * CC * LF;
    float s = 0.f;
    #pragma unroll
    for (int a = 0; a < 2; a++) {
        if ((unsigned)yfv[a] >= 32u) continue;
        #pragma unroll
        for (int b2 = 0; b2 < 2; b2++) {
            if ((unsigned)xfv[b2] >= 32u) continue;
            int tap = pyv[a] * 4 + pxv[b2];
            s += V[((size_t)tap * CC + c) * LF + yfv[a] * 32 + xfv[b2]];
        }
    }
    g_y[((size_t)bi * CC + c) * 4096 + oy * 64 + ox] = 0.25f * s;
}

// -------- implicit-GEMM conv3x3 + bias + ELU (K=1152 tap-major) --------
__global__ __launch_bounds__(256) void k_conv(const float* __restrict__ X,
                                              const float* __restrict__ Wt,
                                              const float* __restrict__ bias,
                                              float* __restrict__ out) {
    int bi = blockIdx.z;
    int n0 = blockIdx.x * BN;                 // 128 spatial = 2 full rows
    int y0 = n0 >> 6;
    __shared__ float As[BK][BM + 4];
    __shared__ float Bs[BK][BN + 4];
    const float* Xb = X + (size_t)bi * CC * HH * WW;
    float acc[8][8] = {};
    int tid = threadIdx.x;
    int tx = tid & 15, ty = tid >> 4;
    for (int k0 = 0; k0 < 1152; k0 += BK) {
        int tap = k0 >> 7;
        int ci0 = k0 & 127;
        int ky = tap / 3 - 1, kx = tap % 3 - 1;
        for (int idx = tid; idx < BK * BM; idx += 256) {
            int mm = idx & 127, kk = idx >> 7;
            As[kk][mm] = Wt[(k0 + kk) * 128 + mm];
        }
        for (int idx = tid; idx < BK * BN; idx += 256) {
            int nn = idx & 127, kk = idx >> 7;
            int dy = nn >> 6, x = nn & 63;
            int sy = y0 + dy + ky, sx = x + kx;
            float v = 0.f;
            if ((unsigned)sy < (unsigned)HH && (unsigned)sx < (unsigned)WW)
                v = Xb[((ci0 + kk) * HH + sy) * WW + sx];
            Bs[kk][nn] = v;
        }
        __syncthreads();
        #pragma unroll
        for (int kk = 0; kk < BK; kk++) {
            float av[8], bv[8];
            #pragma unroll
            for (int i = 0; i < 8; i++) av[i] = As[kk][ty * 8 + i];
            #pragma unroll
            for (int j = 0; j < 8; j++) bv[j] = Bs[kk][tx * 8 + j];
            #pragma unroll
            for (int i = 0; i < 8; i++)
                #pragma unroll
                for (int j = 0; j < 8; j++) acc[i][j] += av[i] * bv[j];
        }
        __syncthreads();
    }
    #pragma unroll
    for (int i = 0; i < 8; i++) {
        int co = ty * 8 + i;
        float bb = bias[co];
        #pragma unroll
        for (int j = 0; j < 8; j++) {
            float v = acc[i][j] + bb;
            v = (v > 0.f) ? v : expm1f(v);
            out[((size_t)bi * CC + co) * 4096 + n0 + tx * 8 + j] = v;
        }
    }
}

// ---------------------------------------------------------------------------
extern "C" void kernel_launch(void* const* d_in, const int* in_sizes, int n_in,
                              void* d_out, int out_size) {
    const float* f  = (const float*)d_in[0];
    const float* b  = (const float*)d_in[1];
    const float* W1 = (const float*)d_in[2];
    const float* b1 = (const float*)d_in[3];
    const float* W2 = (const float*)d_in[4];
    const float* b2 = (const float*)d_in[5];
    float* out = (float*)d_out;

    float* yptr;  cudaGetSymbolAddress((void**)&yptr, g_y);
    float* hptr;  cudaGetSymbolAddress((void**)&hptr, g_h);
    float* w1t;   cudaGetSymbolAddress((void**)&w1t, g_W1t);
    float* w2t;   cudaGetSymbolAddress((void**)&w2t, g_W2t);

    k_down<<<(BQ * CC * HD * HD + 255) / 256, 256>>>(f, b);
    k_norm<<<BQ, 1024>>>();
    k_transW<<<(1152 * 128 + 255) / 256, 256>>>(W1, W2);

    k_gemmG<<<dim3(8, 8, BQ), 256>>>();
    k_S<<<dim3(4096, BQ), 256>>>();
    k_fuse1<<<dim3(4096, BQ), 256>>>();
    k_fuse2<<<dim3(4096, BQ), 256>>>();

    k_sm_part<<<dim3(8, 8, BQ), 128>>>();
    k_sm_comb<<<BQ, 1024>>>();
    k_sm_norm<<<dim3(4096, BQ), 256>>>();

    k_gemmV<<<dim3(8, 16, BQ), 256>>>(b);
    k_comb<<<dim3(2048, BQ), 256>>>();

    k_conv<<<dim3(32, 1, BQ), 256>>>(yptr, w1t, b1, hptr);
    k_conv<<<dim3(32, 1, BQ), 256>>>(hptr, w2t, b2, out);

    (void)in_sizes; (void)n_in; (void)out_size;
}

// round 4
// speedup vs baseline: 4.4611x; 4.4599x over previous
#include <cuda_runtime.h>
#include <cuda_fp16.h>
#include <cstdint>
#include <math.h>

#define BQ 16
#define CC 128
#define LB 1024
#define LF 1024
#define RS 80                   // smem row stride (bytes) — conflict-free for ldmatrix
#define TILEB (128 * RS)        // 10240 bytes per 128x32-f16 tile

// ---------------- device scratch ----------------
__device__ float g_invn[BQ * LB];
__device__ float g_buf1[(size_t)BQ * LB * LF];
__device__ float g_buf2[(size_t)BQ * LB * LF];
__device__ float g_pm[BQ * 8 * LF];
__device__ float g_ps[BQ * 8 * LF];
__device__ float g_mx[BQ * LF];
__device__ float g_rs[BQ * LF];
__device__ float g_V[(size_t)BQ * 16 * LF * CC];

__device__ __align__(16) __half g_bdT_h[(size_t)BQ * LB * CC];
__device__ __align__(16) __half g_bdT_l[(size_t)BQ * LB * CC];
__device__ __align__(16) __half g_fdT_h[(size_t)BQ * LB * CC];
__device__ __align__(16) __half g_fdT_l[(size_t)BQ * LB * CC];
__device__ __align__(16) __half g_bp[(size_t)BQ * 16 * CC * LB];
__device__ __align__(16) __half g_attT[(size_t)BQ * LF * LB];
__device__ __align__(16) __half g_yT[(size_t)BQ * 4096 * CC];
__device__ __align__(16) __half g_hT[(size_t)BQ * 4096 * CC];
__device__ __align__(16) __half g_W1p[CC * 1152];
__device__ __align__(16) __half g_W2p[CC * 1152];

// ---------------- asm helpers ----------------
__device__ __forceinline__ uint32_t s2u(const void* p) {
    uint32_t a;
    asm("{ .reg .u64 t; cvta.to.shared.u64 t, %1; cvt.u32.u64 %0, t; }" : "=r"(a) : "l"(p));
    return a;
}
__device__ __forceinline__ void cp16(uint32_t d, const void* s) {
    asm volatile("cp.async.cg.shared.global [%0], [%1], 16;" :: "r"(d), "l"(s));
}
__device__ __forceinline__ void cp16z(uint32_t d, const void* s, bool ok) {
    int sz = ok ? 16 : 0;
    asm volatile("cp.async.cg.shared.global [%0], [%1], 16, %2;" :: "r"(d), "l"(s), "r"(sz));
}
#define CP_COMMIT asm volatile("cp.async.commit_group;")
#define CP_WAIT1  asm volatile("cp.async.wait_group 1;")
#define CP_WAIT0  asm volatile("cp.async.wait_group 0;")

__device__ __forceinline__ void ldsm4(uint32_t* r, uint32_t a) {
    asm volatile("ldmatrix.sync.aligned.m8n8.x4.shared.b16 {%0,%1,%2,%3}, [%4];"
                 : "=r"(r[0]), "=r"(r[1]), "=r"(r[2]), "=r"(r[3]) : "r"(a));
}
__device__ __forceinline__ void mma16816(float* c, const uint32_t* a, const uint32_t* b) {
    asm volatile(
        "mma.sync.aligned.m16n8k16.row.col.f32.f16.f16.f32 "
        "{%0,%1,%2,%3}, {%4,%5,%6,%7}, {%8,%9}, {%0,%1,%2,%3};"
        : "+f"(c[0]), "+f"(c[1]), "+f"(c[2]), "+f"(c[3])
        : "r"(a[0]), "r"(a[1]), "r"(a[2]), "r"(a[3]), "r"(b[0]), "r"(b[1]));
}
__device__ __forceinline__ void split2h(float v, __half* ph, __half* pl) {
    __half h = __float2half_rn(v);
    *ph = h;
    *pl = __float2half_rn(v - __half2float(h));
}

// A-frag smem address (m16k16, non-trans): rows m..m+15, k-offset kk (tile rows [m][k])
__device__ __forceinline__ uint32_t a_addr(uint32_t tile, int m, int kk, int lane) {
    return tile + (m + (lane & 15)) * RS + (kk + ((lane >> 4) << 3)) * 2;
}
// B-frag smem address (n16k16, non-trans on [n][k]): regs {r0,r1}=n0-7, {r2,r3}=n8-15
__device__ __forceinline__ uint32_t b_addr(uint32_t tile, int n, int kk, int lane) {
    return tile + (n + (lane & 7) + ((lane & 16) >> 1)) * RS + (kk + (lane & 8)) * 2;
}

// warp compute: one K=32 chunk, single pass; acc[4][4][4]
__device__ __forceinline__ void mma_chunk1(uint32_t aT, uint32_t bT, int wm, int wn,
                                           int lane, float acc[4][4][4]) {
    #pragma unroll
    for (int kk = 0; kk < 32; kk += 16) {
        uint32_t a[4][4], bf[2][4];
        #pragma unroll
        for (int mi = 0; mi < 4; mi++) ldsm4(a[mi], a_addr(aT, wm + mi * 16, kk, lane));
        #pragma unroll
        for (int ni = 0; ni < 2; ni++) ldsm4(bf[ni], b_addr(bT, wn + ni * 16, kk, lane));
        #pragma unroll
        for (int mi = 0; mi < 4; mi++)
            #pragma unroll
            for (int nj = 0; nj < 4; nj++)
                mma16816(acc[mi][nj], a[mi], &bf[nj >> 1][(nj & 1) * 2]);
    }
}

// 3-pass split chunk: AhBh + AhBl + AlBh
__device__ __forceinline__ void mma_chunk3(uint32_t AhT, uint32_t AlT, uint32_t BhT,
                                           uint32_t BlT, int wm, int wn, int lane,
                                           float acc[4][4][4]) {
    #pragma unroll
    for (int kk = 0; kk < 32; kk += 16) {
        uint32_t ah[4][4], al[4][4], bh[2][4], bl[2][4];
        #pragma unroll
        for (int mi = 0; mi < 4; mi++) {
            ldsm4(ah[mi], a_addr(AhT, wm + mi * 16, kk, lane));
            ldsm4(al[mi], a_addr(AlT, wm + mi * 16, kk, lane));
        }
        #pragma unroll
        for (int ni = 0; ni < 2; ni++) {
            ldsm4(bh[ni], b_addr(BhT, wn + ni * 16, kk, lane));
            ldsm4(bl[ni], b_addr(BlT, wn + ni * 16, kk, lane));
        }
        #pragma unroll
        for (int mi = 0; mi < 4; mi++)
            #pragma unroll
            for (int nj = 0; nj < 4; nj++) {
                mma16816(acc[mi][nj], ah[mi], &bh[nj >> 1][(nj & 1) * 2]);
                mma16816(acc[mi][nj], ah[mi], &bl[nj >> 1][(nj & 1) * 2]);
                mma16816(acc[mi][nj], al[mi], &bh[nj >> 1][(nj & 1) * 2]);
            }
    }
}

// ---------------- pack / elementwise ----------------
__global__ void k_norm(const float* __restrict__ b) {
    int bi = blockIdx.x, p = threadIdx.x;
    __shared__ float sq[LB];
    int y = p >> 5, x = p & 31;
    const float* bb = b + (size_t)bi * CC * 4096 + (2 * y) * 64 + 2 * x;
    float s = 0.f;
    for (int c = 0; c < CC; c++) { float v = bb[(size_t)c * 4096]; s += v * v; }
    sq[p] = s;
    __syncthreads();
    float ns = 0.f;
    #pragma unroll
    for (int dy = -1; dy <= 1; dy++)
        #pragma unroll
        for (int dx = -1; dx <= 1; dx++) {
            int y2 = y + dy, x2 = x + dx;
            if ((unsigned)y2 < 32u && (unsigned)x2 < 32u) ns += sq[(y2 << 5) + x2];
        }
    float n = sqrtf(ns); if (n < 1e-4f) n = 1e-4f;
    g_invn[bi * LB + p] = 1.0f / n;
}

__global__ void k_pack_down(const float* __restrict__ f, const float* __restrict__ b) {
    size_t i = (size_t)blockIdx.x * 256 + threadIdx.x;
    if (i >= (size_t)BQ * LB * CC) return;
    int c = i & 127;
    int p = (i >> 7) & 1023;
    int bi = i >> 17;
    int y = p >> 5, x = p & 31;
    size_t src = ((size_t)(bi * CC + c) * 64 + 2 * y) * 64 + 2 * x;
    split2h(f[src], &g_fdT_h[i], &g_fdT_l[i]);
    split2h(b[src], &g_bdT_h[i], &g_bdT_l[i]);
}

__global__ void k_pack_bshift(const float* __restrict__ b) {
    size_t i = (size_t)blockIdx.x * 256 + threadIdx.x;
    if (i >= (size_t)BQ * 16 * CC * LB) return;
    int lb = i & 1023;
    int c = (i >> 10) & 127;
    int tap = (i >> 17) & 15;
    int bi = i >> 21;
    int py = tap >> 2, px = tap & 3;
    int row = 2 * (lb >> 5) + py - 1, col = 2 * (lb & 31) + px - 1;
    float v = 0.f;
    if ((unsigned)row < 64u && (unsigned)col < 64u)
        v = b[((size_t)(bi * CC + c) * 64 + row) * 64 + col];
    g_bp[i] = __float2half_rn(v);
}

__global__ void k_packW(const float* __restrict__ W1, const float* __restrict__ W2) {
    int i = blockIdx.x * 256 + threadIdx.x;
    if (i >= CC * 1152) return;
    int k = i % 1152, co = i / 1152;
    int tap = k >> 7, ci = k & 127;
    int src = (co * 128 + ci) * 9 + tap;
    g_W1p[i] = __float2half_rn(W1[src]);
    g_W2p[i] = __float2half_rn(W2[src]);
}

__global__ void k_S() {
    int bi = blockIdx.y;
    int i = blockIdx.x * 256 + threadIdx.x;
    int pb = i >> 10, pf = i & 1023;
    int yb = pb >> 5, xb = pb & 31, yf = pf >> 5, xf = pf & 31;
    const float* G = g_buf1 + ((size_t)bi << 20);
    float s = 0.f;
    #pragma unroll
    for (int dy = -1; dy <= 1; dy++)
        #pragma unroll
        for (int dx = -1; dx <= 1; dx++) {
            int a = yb + dy, b2 = xb + dx, c = yf + dy, d = xf + dx;
            if ((unsigned)a < 32u && (unsigned)b2 < 32u && (unsigned)c < 32u && (unsigned)d < 32u)
                s += G[((a << 5) + b2) * LF + (c << 5) + d];
        }
    g_buf2[((size_t)bi << 20) + i] = s * g_invn[bi * LB + pb];
}

__global__ void k_fuse1() {
    int bi = blockIdx.y;
    int i = blockIdx.x * 256 + threadIdx.x;
    int lb = i >> 10, lf = i & 1023;
    const float* S = g_buf2 + ((size_t)bi << 20);
    float s = 0.f;
    #pragma unroll
    for (int k = -1; k <= 1; k++) {
        int a = lb + k, c = lf + k;
        if ((unsigned)a < 1024u && (unsigned)c < 1024u) s += S[a * LF + c];
    }
    g_buf1[((size_t)bi << 20) + i] = s;
}

__global__ void k_fuse2() {
    int bi = blockIdx.y;
    int i = blockIdx.x * 256 + threadIdx.x;
    int lb = i >> 10, lf = i & 1023;
    int hb = lb >> 5, wb = lb & 31, hf = lf >> 5, wf = lf & 31;
    int lbT = wb * 32 + hb, lfT = wf * 32 + hf;
    const float* F1 = g_buf1 + ((size_t)bi << 20);
    float s = 0.f;
    #pragma unroll
    for (int k = -1; k <= 1; k++) {
        int a = lbT + k, c = lfT + k;
        if ((unsigned)a < 1024u && (unsigned)c < 1024u) {
            int wb2 = a >> 5, hb2 = a & 31, wf2 = c >> 5, hf2 = c & 31;
            s += F1[(hb2 * 32 + wb2) * LF + hf2 * 32 + wf2];
        }
    }
    g_buf2[((size_t)bi << 20) + i] = s;
}

__global__ void k_sm_part() {
    int bi = blockIdx.z, lbc = blockIdx.y;
    int lf = blockIdx.x * 128 + threadIdx.x;
    const float* F = g_buf2 + ((size_t)bi << 20);
    float m = -1e30f, s = 0.f;
    for (int l = lbc * 128; l < lbc * 128 + 128; l++) {
        float v = 10.0f * F[l * LF + lf];
        if (v > m) { s = s * expf(m - v) + 1.0f; m = v; }
        else s += expf(v - m);
    }
    g_pm[(bi * 8 + lbc) * LF + lf] = m;
    g_ps[(bi * 8 + lbc) * LF + lf] = s;
}

__global__ void k_sm_comb() {
    int bi = blockIdx.x, lf = threadIdx.x;
    float m = -1e30f;
    for (int c = 0; c < 8; c++) { float v = g_pm[(bi * 8 + c) * LF + lf]; if (v > m) m = v; }
    float s = 0.f;
    for (int c = 0; c < 8; c++)
        s += g_ps[(bi * 8 + c) * LF + lf] * expf(g_pm[(bi * 8 + c) * LF + lf] - m);
    g_mx[bi * LF + lf] = m;
    g_rs[bi * LF + lf] = 1.0f / s;
}

// softmax-normalize + transpose -> attT[lf][lb] (half)
__global__ void k_sm_normT() {
    __shared__ float t[32][33];
    int bi = blockIdx.z;
    int lf0 = blockIdx.x * 32, lb0 = blockIdx.y * 32;
    int c = threadIdx.x & 31, r0 = threadIdx.x >> 5;
    const float* F = g_buf2 + ((size_t)bi << 20);
    #pragma unroll
    for (int it = 0; it < 4; it++) {
        int r = r0 + it * 8;
        float v = 10.0f * F[(lb0 + r) * LF + lf0 + c];
        t[r][c] = expf(v - g_mx[bi * LF + lf0 + c]) * g_rs[bi * LF + lf0 + c];
    }
    __syncthreads();
    #pragma unroll
    for (int it = 0; it < 4; it++) {
        int r = r0 + it * 8;
        g_attT[((size_t)(bi * LF + lf0 + r)) * LB + lb0 + c] = __float2half_rn(t[c][r]);
    }
}

// combine V -> yT[pix][c] (half)
__global__ void k_comb_pack() {
    size_t i = (size_t)blockIdx.x * 256 + threadIdx.x;
    if (i >= (size_t)BQ * 4096 * CC) return;
    int c = i & 127;
    int pix = (i >> 7) & 4095;
    int bi = i >> 19;
    int oy = pix >> 6, ox = pix & 63;
    int my = oy >> 1, mx = ox >> 1;
    int yfv[2], pyv[2], xfv[2], pxv[2];
    if (oy & 1) { yfv[0] = my; pyv[0] = 2; yfv[1] = my + 1; pyv[1] = 0; }
    else        { yfv[0] = my; pyv[0] = 1; yfv[1] = my - 1; pyv[1] = 3; }
    if (ox & 1) { xfv[0] = mx; pxv[0] = 2; xfv[1] = mx + 1; pxv[1] = 0; }
    else        { xfv[0] = mx; pxv[0] = 1; xfv[1] = mx - 1; pxv[1] = 3; }
    float s = 0.f;
    #pragma unroll
    for (int a = 0; a < 2; a++) {
        if ((unsigned)yfv[a] >= 32u) continue;
        #pragma unroll
        for (int b2 = 0; b2 < 2; b2++) {
            if ((unsigned)xfv[b2] >= 32u) continue;
            int tap = pyv[a] * 4 + pxv[b2];
            int lf = yfv[a] * 32 + xfv[b2];
            s += g_V[((size_t)(bi * 16 + tap) * LF + lf) * CC + c];
        }
    }
    g_yT[i] = __float2half_rn(0.25f * s);
}

// ---------------- mma GEMM kernels ----------------
// G[pb][pf] = bdT(split) @ fdT(split)^T, K=128, 3-pass
__global__ __launch_bounds__(256) void k_mmaG() {
    extern __shared__ char smc[];
    uint32_t sb = s2u(smc);
    int tid = threadIdx.x, lane = tid & 31, warp = tid >> 5;
    int bi = blockIdx.z, m0 = blockIdx.y * 128, n0 = blockIdx.x * 128;
    int wm = (warp >> 2) * 64, wn = (warp & 3) * 32;
    const char* srcs[4] = {
        (const char*)g_bdT_h + (size_t)(bi * LB + m0) * 256,
        (const char*)g_bdT_l + (size_t)(bi * LB + m0) * 256,
        (const char*)g_fdT_h + (size_t)(bi * LB + n0) * 256,
        (const char*)g_fdT_l + (size_t)(bi * LB + n0) * 256};
    float acc[4][4][4] = {};
    #pragma unroll 1
    for (int pre = 0; pre < 1; pre++) {
        for (int u = tid; u < 2048; u += 256) {
            int t = u >> 9, idx = u & 511, r = idx >> 2, c4 = idx & 3;
            cp16(sb + t * TILEB + r * RS + c4 * 16, srcs[t] + (size_t)r * 256 + c4 * 16);
        }
        CP_COMMIT;
    }
    for (int i = 0; i < 4; i++) {
        if (i + 1 < 4) {
            int s = (i + 1) & 1;
            for (int u = tid; u < 2048; u += 256) {
                int t = u >> 9, idx = u & 511, r = idx >> 2, c4 = idx & 3;
                cp16(sb + (s * 4 + t) * TILEB + r * RS + c4 * 16,
                     srcs[t] + (size_t)r * 256 + (i + 1) * 64 + c4 * 16);
            }
            CP_COMMIT;
            CP_WAIT1;
        } else {
            CP_WAIT0;
        }
        __syncthreads();
        uint32_t base = sb + (i & 1) * 4 * TILEB;
        mma_chunk3(base, base + TILEB, base + 2 * TILEB, base + 3 * TILEB, wm, wn, lane, acc);
        __syncthreads();
    }
    float* out = g_buf1 + ((size_t)bi << 20);
    #pragma unroll
    for (int mi = 0; mi < 4; mi++)
        #pragma unroll
        for (int nj = 0; nj < 4; nj++) {
            int grow = m0 + wm + mi * 16 + (lane >> 2);
            int gcol = n0 + wn + nj * 8 + (lane & 3) * 2;
            *(float2*)&out[(size_t)grow * LF + gcol] = make_float2(acc[mi][nj][0], acc[mi][nj][1]);
            *(float2*)&out[(size_t)(grow + 8) * LF + gcol] = make_float2(acc[mi][nj][2], acc[mi][nj][3]);
        }
}

// V[tap][lf][c] = attT[lf][:] . bp[tap][c][:]  (M=lf, N=c, K=1024, single pass)
__global__ __launch_bounds__(256) void k_mmaV() {
    extern __shared__ char smc[];
    uint32_t sb = s2u(smc);
    int tid = threadIdx.x, lane = tid & 31, warp = tid >> 5;
    int bi = blockIdx.z, tap = blockIdx.y, m0 = blockIdx.x * 128;
    int wm = (warp >> 2) * 64, wn = (warp & 3) * 32;
    const char* srcA = (const char*)g_attT + (size_t)(bi * LF + m0) * 2048;
    const char* srcB = (const char*)g_bp + (size_t)((bi * 16 + tap) * CC) * 2048;
    float acc[4][4][4] = {};
    const int NC = 32;
    for (int u = tid; u < 1024; u += 256) {
        int t = u >> 9, idx = u & 511, r = idx >> 2, c4 = idx & 3;
        cp16(sb + t * TILEB + r * RS + c4 * 16,
             (t ? srcB : srcA) + (size_t)r * 2048 + c4 * 16);
    }
    CP_COMMIT;
    for (int i = 0; i < NC; i++) {
        if (i + 1 < NC) {
            int s = (i + 1) & 1;
            for (int u = tid; u < 1024; u += 256) {
                int t = u >> 9, idx = u & 511, r = idx >> 2, c4 = idx & 3;
                cp16(sb + (s * 2 + t) * TILEB + r * RS + c4 * 16,
                     (t ? srcB : srcA) + (size_t)r * 2048 + (i + 1) * 64 + c4 * 16);
            }
            CP_COMMIT;
            CP_WAIT1;
        } else {
            CP_WAIT0;
        }
        __syncthreads();
        uint32_t base = sb + (i & 1) * 2 * TILEB;
        mma_chunk1(base, base + TILEB, wm, wn, lane, acc);
        __syncthreads();
    }
    float* out = g_V + (size_t)(bi * 16 + tap) * LF * CC;
    #pragma unroll
    for (int mi = 0; mi < 4; mi++)
        #pragma unroll
        for (int nj = 0; nj < 4; nj++) {
            int glf = m0 + wm + mi * 16 + (lane >> 2);
            int gc = wn + nj * 8 + (lane & 3) * 2;
            *(float2*)&out[(size_t)glf * CC + gc] = make_float2(acc[mi][nj][0], acc[mi][nj][1]);
            *(float2*)&out[(size_t)(glf + 8) * CC + gc] = make_float2(acc[mi][nj][2], acc[mi][nj][3]);
        }
}

// conv3x3 implicit GEMM: M=128 pixels, N=128 co, K=1152 (36 chunks)
__global__ __launch_bounds__(256) void k_mmaConv(
    const __half* __restrict__ X, const __half* __restrict__ Wp,
    const float* __restrict__ bias, float* __restrict__ fout, int mode) {
    extern __shared__ char smc[];
    uint32_t sb = s2u(smc);
    int tid = threadIdx.x, lane = tid & 31, warp = tid >> 5;
    int bi = blockIdx.z, n0 = blockIdx.x * 128;
    int wm = (warp >> 2) * 64, wn = (warp & 3) * 32;
    const char* Xb = (const char*)X + (size_t)bi * 4096 * 256;
    const char* Wb = (const char*)Wp;
    float acc[4][4][4] = {};
    const int NC = 36;
    // stage chunk ch into stage s
    auto stageC = [&](int ch, int s) {
        int tap = ch >> 2, ci0 = (ch & 3) * 32;
        int ky = tap / 3 - 1, kx = tap % 3 - 1;
        for (int u = tid; u < 1024; u += 256) {
            int t = u >> 9, idx = u & 511, r = idx >> 2, c4 = idx & 3;
            uint32_t dst = sb + (s * 2 + t) * TILEB + r * RS + c4 * 16;
            if (t) {
                cp16(dst, Wb + (size_t)r * 2304 + (tap * 128 + ci0) * 2 + c4 * 16);
            } else {
                int p = n0 + r;
                int sy = (p >> 6) + ky, sx = (p & 63) + kx;
                bool ok = (unsigned)sy < 64u && (unsigned)sx < 64u;
                int sp = ok ? sy * 64 + sx : 0;
                cp16z(dst, Xb + (size_t)sp * 256 + ci0 * 2 + c4 * 16, ok);
            }
        }
        CP_COMMIT;
    };
    stageC(0, 0);
    for (int i = 0; i < NC; i++) {
        if (i + 1 < NC) { stageC(i + 1, (i + 1) & 1); CP_WAIT1; }
        else CP_WAIT0;
        __syncthreads();
        uint32_t base = sb + (i & 1) * 2 * TILEB;
        mma_chunk1(base, base + TILEB, wm, wn, lane, acc);
        __syncthreads();
    }
    if (mode == 0) {
        #pragma unroll
        for (int mi = 0; mi < 4; mi++)
            #pragma unroll
            for (int nj = 0; nj < 4; nj++) {
                int pr = wm + mi * 16 + (lane >> 2);
                int col = wn + nj * 8 + (lane & 3) * 2;
                float b0 = bias[col], b1 = bias[col + 1];
                float v0 = acc[mi][nj][0] + b0, v1 = acc[mi][nj][1] + b1;
                float v2 = acc[mi][nj][2] + b0, v3 = acc[mi][nj][3] + b1;
                v0 = v0 > 0.f ? v0 : expm1f(v0);
                v1 = v1 > 0.f ? v1 : expm1f(v1);
                v2 = v2 > 0.f ? v2 : expm1f(v2);
                v3 = v3 > 0.f ? v3 : expm1f(v3);
                __half2* o0 = (__half2*)&g_hT[((size_t)bi * 4096 + n0 + pr) * 128 + col];
                __half2* o1 = (__half2*)&g_hT[((size_t)bi * 4096 + n0 + pr + 8) * 128 + col];
                *o0 = __halves2half2(__float2half_rn(v0), __float2half_rn(v1));
                *o1 = __halves2half2(__float2half_rn(v2), __float2half_rn(v3));
            }
    } else {
        float* sd = (float*)smc;
        #pragma unroll
        for (int mi = 0; mi < 4; mi++)
            #pragma unroll
            for (int nj = 0; nj < 4; nj++) {
                int pr = wm + mi * 16 + (lane >> 2);
                int col = wn + nj * 8 + (lane & 3) * 2;
                float b0 = bias[col], b1 = bias[col + 1];
                float v0 = acc[mi][nj][0] + b0, v1 = acc[mi][nj][1] + b1;
                float v2 = acc[mi][nj][2] + b0, v3 = acc[mi][nj][3] + b1;
                sd[pr * 129 + col] = v0 > 0.f ? v0 : expm1f(v0);
                sd[pr * 129 + col + 1] = v1 > 0.f ? v1 : expm1f(v1);
                sd[(pr + 8) * 129 + col] = v2 > 0.f ? v2 : expm1f(v2);
                sd[(pr + 8) * 129 + col + 1] = v3 > 0.f ? v3 : expm1f(v3);
            }
        __syncthreads();
        for (int u = tid; u < 16384; u += 256) {
            int pix = u & 127, co = u >> 7;
            fout[((size_t)bi * 128 + co) * 4096 + n0 + pix] = sd[pix * 129 + co];
        }
    }
}

// ---------------------------------------------------------------------------
extern "C" void kernel_launch(void* const* d_in, const int* in_sizes, int n_in,
                              void* d_out, int out_size) {
    const float* f  = (const float*)d_in[0];
    const float* b  = (const float*)d_in[1];
    const float* W1 = (const float*)d_in[2];
    const float* b1 = (const float*)d_in[3];
    const float* W2 = (const float*)d_in[4];
    const float* b2 = (const float*)d_in[5];
    float* out = (float*)d_out;

    cudaFuncSetAttribute(k_mmaG, cudaFuncAttributeMaxDynamicSharedMemorySize, 8 * TILEB);
    cudaFuncSetAttribute(k_mmaV, cudaFuncAttributeMaxDynamicSharedMemorySize, 4 * TILEB);
    cudaFuncSetAttribute(k_mmaConv, cudaFuncAttributeMaxDynamicSharedMemorySize, 67072);

    __half *yh, *hh, *w1p, *w2p;
    cudaGetSymbolAddress((void**)&yh, g_yT);
    cudaGetSymbolAddress((void**)&hh, g_hT);
    cudaGetSymbolAddress((void**)&w1p, g_W1p);
    cudaGetSymbolAddress((void**)&w2p, g_W2p);

    k_norm<<<BQ, 1024>>>(b);
    k_pack_down<<<(int)(((size_t)BQ * LB * CC + 255) / 256), 256>>>(f, b);
    k_pack_bshift<<<(int)(((size_t)BQ * 16 * CC * LB + 255) / 256), 256>>>(b);
    k_packW<<<(CC * 1152 + 255) / 256, 256>>>(W1, W2);

    k_mmaG<<<dim3(8, 8, BQ), 256, 8 * TILEB>>>();
    k_S<<<dim3(4096, BQ), 256>>>();
    k_fuse1<<<dim3(4096, BQ), 256>>>();
    k_fuse2<<<dim3(4096, BQ), 256>>>();
    k_sm_part<<<dim3(8, 8, BQ), 128>>>();
    k_sm_comb<<<BQ, 1024>>>();
    k_sm_normT<<<dim3(32, 32, BQ), 256>>>();

    k_mmaV<<<dim3(8, 16, BQ), 256, 4 * TILEB>>>();
    k_comb_pack<<<(int)(((size_t)BQ * 4096 * CC + 255) / 256), 256>>>();

    k_mmaConv<<<dim3(32, 1, BQ), 256, 67072>>>(yh, w1p, b1, nullptr, 0);
    k_mmaConv<<<dim3(32, 1, BQ), 256, 67072>>>(hh, w2p, b2, out, 1);

    (void)in_sizes; (void)n_in; (void)out_size;
}

// round 5
// speedup vs baseline: 4.6991x; 1.0533x over previous
#include <cuda_runtime.h>
#include <cuda_fp16.h>
#include <cstdint>
#include <math.h>

#define BQ 16
#define CC 128
#define LB 1024
#define LF 1024
#define RS 80                   // smem row stride (bytes) — conflict-free ldmatrix
#define TILEB (128 * RS)        // 10240 bytes per 128x32-f16 tile

// ---------------- device scratch ----------------
__device__ float g_invn[BQ * LB];
__device__ float g_buf1[(size_t)BQ * LB * LF];   // GT, then F2T
__device__ float g_buf2[(size_t)BQ * LB * LF];   // ST
__device__ float g_V[(size_t)BQ * 16 * LF * CC];

__device__ __align__(16) __half g_bdT_h[(size_t)BQ * LB * CC];
__device__ __align__(16) __half g_bdT_l[(size_t)BQ * LB * CC];
__device__ __align__(16) __half g_fdT_h[(size_t)BQ * LB * CC];
__device__ __align__(16) __half g_fdT_l[(size_t)BQ * LB * CC];
__device__ __align__(16) __half g_bp[(size_t)BQ * 16 * CC * LB];
__device__ __align__(16) __half g_attT[(size_t)BQ * LF * LB];
__device__ __align__(16) __half g_yT[(size_t)BQ * 4096 * CC];
__device__ __align__(16) __half g_hT[(size_t)BQ * 4096 * CC];
__device__ __align__(16) __half g_W1p[CC * 1152];
__device__ __align__(16) __half g_W2p[CC * 1152];

// ---------------- asm helpers ----------------
__device__ __forceinline__ uint32_t s2u(const void* p) {
    uint32_t a;
    asm("{ .reg .u64 t; cvta.to.shared.u64 t, %1; cvt.u32.u64 %0, t; }" : "=r"(a) : "l"(p));
    return a;
}
__device__ __forceinline__ void cp16(uint32_t d, const void* s) {
    asm volatile("cp.async.cg.shared.global [%0], [%1], 16;" :: "r"(d), "l"(s));
}
__device__ __forceinline__ void cp16z(uint32_t d, const void* s, bool ok) {
    int sz = ok ? 16 : 0;
    asm volatile("cp.async.cg.shared.global [%0], [%1], 16, %2;" :: "r"(d), "l"(s), "r"(sz));
}
#define CP_COMMIT asm volatile("cp.async.commit_group;")
#define CP_WAIT1  asm volatile("cp.async.wait_group 1;")

__device__ __forceinline__ void ldsm4(uint32_t* r, uint32_t a) {
    asm volatile("ldmatrix.sync.aligned.m8n8.x4.shared.b16 {%0,%1,%2,%3}, [%4];"
                 : "=r"(r[0]), "=r"(r[1]), "=r"(r[2]), "=r"(r[3]) : "r"(a));
}
__device__ __forceinline__ void mma16816(float* c, const uint32_t* a, const uint32_t* b) {
    asm volatile(
        "mma.sync.aligned.m16n8k16.row.col.f32.f16.f16.f32 "
        "{%0,%1,%2,%3}, {%4,%5,%6,%7}, {%8,%9}, {%0,%1,%2,%3};"
        : "+f"(c[0]), "+f"(c[1]), "+f"(c[2]), "+f"(c[3])
        : "r"(a[0]), "r"(a[1]), "r"(a[2]), "r"(a[3]), "r"(b[0]), "r"(b[1]));
}
__device__ __forceinline__ void split2h(float v, __half* ph, __half* pl) {
    __half h = __float2half_rn(v);
    *ph = h;
    *pl = __float2half_rn(v - __half2float(h));
}

__device__ __forceinline__ uint32_t a_addr(uint32_t tile, int m, int kk, int lane) {
    return tile + (m + (lane & 15)) * RS + (kk + ((lane >> 4) << 3)) * 2;
}
__device__ __forceinline__ uint32_t b_addr(uint32_t tile, int n, int kk, int lane) {
    return tile + (n + (lane & 7) + ((lane & 16) >> 1)) * RS + (kk + (lane & 8)) * 2;
}

__device__ __forceinline__ void mma_chunk1(uint32_t aT, uint32_t bT, int wm, int wn,
                                           int lane, float acc[4][4][4]) {
    #pragma unroll
    for (int kk = 0; kk < 32; kk += 16) {
        uint32_t a[4][4], bf[2][4];
        #pragma unroll
        for (int mi = 0; mi < 4; mi++) ldsm4(a[mi], a_addr(aT, wm + mi * 16, kk, lane));
        #pragma unroll
        for (int ni = 0; ni < 2; ni++) ldsm4(bf[ni], b_addr(bT, wn + ni * 16, kk, lane));
        #pragma unroll
        for (int mi = 0; mi < 4; mi++)
            #pragma unroll
            for (int nj = 0; nj < 4; nj++)
                mma16816(acc[mi][nj], a[mi], &bf[nj >> 1][(nj & 1) * 2]);
    }
}

__device__ __forceinline__ void mma_chunk3(uint32_t AhT, uint32_t AlT, uint32_t BhT,
                                           uint32_t BlT, int wm, int wn, int lane,
                                           float acc[4][4][4]) {
    #pragma unroll
    for (int kk = 0; kk < 32; kk += 16) {
        uint32_t ah[4][4], al[4][4], bh[2][4], bl[2][4];
        #pragma unroll
        for (int mi = 0; mi < 4; mi++) {
            ldsm4(ah[mi], a_addr(AhT, wm + mi * 16, kk, lane));
            ldsm4(al[mi], a_addr(AlT, wm + mi * 16, kk, lane));
        }
        #pragma unroll
        for (int ni = 0; ni < 2; ni++) {
            ldsm4(bh[ni], b_addr(BhT, wn + ni * 16, kk, lane));
            ldsm4(bl[ni], b_addr(BlT, wn + ni * 16, kk, lane));
        }
        #pragma unroll
        for (int mi = 0; mi < 4; mi++)
            #pragma unroll
            for (int nj = 0; nj < 4; nj++) {
                mma16816(acc[mi][nj], ah[mi], &bh[nj >> 1][(nj & 1) * 2]);
                mma16816(acc[mi][nj], ah[mi], &bl[nj >> 1][(nj & 1) * 2]);
                mma16816(acc[mi][nj], al[mi], &bh[nj >> 1][(nj & 1) * 2]);
            }
    }
}

// ---------------- pack / elementwise ----------------
__global__ void k_norm(const float* __restrict__ b) {
    int bi = blockIdx.x, p = threadIdx.x;
    __shared__ float sq[LB];
    int y = p >> 5, x = p & 31;
    const float* bb = b + (size_t)bi * CC * 4096 + (2 * y) * 64 + 2 * x;
    float s = 0.f;
    for (int c = 0; c < CC; c++) { float v = bb[(size_t)c * 4096]; s += v * v; }
    sq[p] = s;
    __syncthreads();
    float ns = 0.f;
    #pragma unroll
    for (int dy = -1; dy <= 1; dy++)
        #pragma unroll
        for (int dx = -1; dx <= 1; dx++) {
            int y2 = y + dy, x2 = x + dx;
            if ((unsigned)y2 < 32u && (unsigned)x2 < 32u) ns += sq[(y2 << 5) + x2];
        }
    float n = sqrtf(ns); if (n < 1e-4f) n = 1e-4f;
    g_invn[bi * LB + p] = 1.0f / n;
}

// pack fd/bd -> [p][c] hi/lo, via smem transpose (coalesced both sides)
__global__ void k_pack_down(const float* __restrict__ f, const float* __restrict__ b) {
    __shared__ float tf[32][33], tb[32][33];
    int bi = blockIdx.z;
    int yb = blockIdx.x;                  // p-tile: p = yb*32 + x
    int c0 = blockIdx.y * 32;
    int lane = threadIdx.x & 31, w = threadIdx.x >> 5;
    for (int yy = w; yy < 32; yy += 8) {
        size_t src = ((size_t)(bi * CC + c0 + yy) * 64 + 2 * yb) * 64 + 2 * lane;
        tf[yy][lane] = f[src];
        tb[yy][lane] = b[src];
    }
    __syncthreads();
    for (int yy = w; yy < 32; yy += 8) {
        size_t o = ((size_t)(bi * 1024 + yb * 32 + yy)) * 128 + c0 + lane;
        split2h(tf[lane][yy], &g_fdT_h[o], &g_fdT_l[o]);
        split2h(tb[lane][yy], &g_bdT_h[o], &g_bdT_l[o]);
    }
}

__global__ void k_pack_bshift(const float* __restrict__ b) {
    size_t i = (size_t)blockIdx.x * 256 + threadIdx.x;
    if (i >= (size_t)BQ * 16 * CC * LB) return;
    int lb = i & 1023;
    int c = (i >> 10) & 127;
    int tap = (i >> 17) & 15;
    int bi = i >> 21;
    int py = tap >> 2, px = tap & 3;
    int row = 2 * (lb >> 5) + py - 1, col = 2 * (lb & 31) + px - 1;
    float v = 0.f;
    if ((unsigned)row < 64u && (unsigned)col < 64u)
        v = b[((size_t)(bi * CC + c) * 64 + row) * 64 + col];
    g_bp[i] = __float2half_rn(v);
}

__global__ void k_packW(const float* __restrict__ W1, const float* __restrict__ W2) {
    int i = blockIdx.x * 256 + threadIdx.x;
    if (i >= CC * 1152) return;
    int k = i % 1152, co = i / 1152;
    int tap = k >> 7, ci = k & 127;
    int src = (co * 128 + ci) * 9 + tap;
    g_W1p[i] = __float2half_rn(W1[src]);
    g_W2p[i] = __float2half_rn(W2[src]);
}

// ST[pf][pb] = invn[pb] * 9-tap diag stencil of GT (GT[pf][pb] in buf1) -> buf2
__global__ void k_ST() {
    int bi = blockIdx.y;
    int i = blockIdx.x * 256 + threadIdx.x;
    int pb = i & 1023, pf = i >> 10;
    int yb = pb >> 5, xb = pb & 31, yf = pf >> 5, xf = pf & 31;
    const float* GT = g_buf1 + ((size_t)bi << 20);
    float s = 0.f;
    #pragma unroll
    for (int dy = -1; dy <= 1; dy++)
        #pragma unroll
        for (int dx = -1; dx <= 1; dx++) {
            int a = yb + dy, b2 = xb + dx, c = yf + dy, d = xf + dx;
            if ((unsigned)a < 32u && (unsigned)b2 < 32u && (unsigned)c < 32u && (unsigned)d < 32u)
                s += GT[((c << 5) + d) * LB + (a << 5) + b2];
        }
    g_buf2[((size_t)bi << 20) + i] = s * g_invn[bi * LB + pb];
}

// F2T[lf][lb] = fuse2(fuse1(S)) composed, reading ST (buf2) -> buf1
__global__ void k_fuse12T() {
    int bi = blockIdx.y;
    int i = blockIdx.x * 256 + threadIdx.x;
    int lb = i & 1023, lf = i >> 10;
    int lbT = ((lb & 31) << 5) + (lb >> 5);
    int lfT = ((lf & 31) << 5) + (lf >> 5);
    const float* ST = g_buf2 + ((size_t)bi << 20);
    float s = 0.f;
    #pragma unroll
    for (int j = -1; j <= 1; j++) {
        int a = lbT + j, b2 = lfT + j;
        if ((unsigned)a < 1024u && (unsigned)b2 < 1024u) {
            int r = ((a & 31) << 5) + (a >> 5);
            int c = ((b2 & 31) << 5) + (b2 >> 5);
            #pragma unroll
            for (int k = -1; k <= 1; k++) {
                int rr = r + k, cc = c + k;
                if ((unsigned)rr < 1024u && (unsigned)cc < 1024u)
                    s += ST[cc * LB + rr];
            }
        }
    }
    g_buf1[((size_t)bi << 20) + i] = s;
}

// row softmax over F2T rows (x10 scale) -> attT[lf][lb] half
__global__ __launch_bounds__(256) void k_softmaxT() {
    int bi = blockIdx.y;
    int row = blockIdx.x * 8 + (threadIdx.x >> 5);
    int lane = threadIdx.x & 31;
    const float* R = g_buf1 + ((size_t)bi << 20) + (size_t)row * 1024;
    float v[32];
    float m = -1e30f;
    #pragma unroll
    for (int t = 0; t < 32; t++) { v[t] = 10.0f * R[t * 32 + lane]; m = fmaxf(m, v[t]); }
    #pragma unroll
    for (int o = 16; o; o >>= 1) m = fmaxf(m, __shfl_xor_sync(0xFFFFFFFFu, m, o));
    float s = 0.f;
    #pragma unroll
    for (int t = 0; t < 32; t++) { v[t] = expf(v[t] - m); s += v[t]; }
    #pragma unroll
    for (int o = 16; o; o >>= 1) s += __shfl_xor_sync(0xFFFFFFFFu, s, o);
    float inv = 1.0f / s;
    __half* O = g_attT + (size_t)(bi * LF + row) * 1024;
    #pragma unroll
    for (int t = 0; t < 32; t++) O[t * 32 + lane] = __float2half_rn(v[t] * inv);
}

// combine V -> yT[pix][c] (half)
__global__ void k_comb_pack() {
    size_t i = (size_t)blockIdx.x * 256 + threadIdx.x;
    if (i >= (size_t)BQ * 4096 * CC) return;
    int c = i & 127;
    int pix = (i >> 7) & 4095;
    int bi = i >> 19;
    int oy = pix >> 6, ox = pix & 63;
    int my = oy >> 1, mx = ox >> 1;
    int yfv[2], pyv[2], xfv[2], pxv[2];
    if (oy & 1) { yfv[0] = my; pyv[0] = 2; yfv[1] = my + 1; pyv[1] = 0; }
    else        { yfv[0] = my; pyv[0] = 1; yfv[1] = my - 1; pyv[1] = 3; }
    if (ox & 1) { xfv[0] = mx; pxv[0] = 2; xfv[1] = mx + 1; pxv[1] = 0; }
    else        { xfv[0] = mx; pxv[0] = 1; xfv[1] = mx - 1; pxv[1] = 3; }
    float s = 0.f;
    #pragma unroll
    for (int a = 0; a < 2; a++) {
        if ((unsigned)yfv[a] >= 32u) continue;
        #pragma unroll
        for (int b2 = 0; b2 < 2; b2++) {
            if ((unsigned)xfv[b2] >= 32u) continue;
            int tap = pyv[a] * 4 + pxv[b2];
            int lf = yfv[a] * 32 + xfv[b2];
            s += g_V[((size_t)(bi * 16 + tap) * LF + lf) * CC + c];
        }
    }
    g_yT[i] = __float2half_rn(0.25f * s);
}

// ---------------- mma GEMM kernels (3-stage, single sync/chunk) ----------------
// GT[pf][pb] = fdT(split) @ bdT(split)^T, K=128 (4 chunks, 3-pass)
__global__ __launch_bounds__(256) void k_mmaG() {
    extern __shared__ char smc[];
    uint32_t sb = s2u(smc);
    int tid = threadIdx.x, lane = tid & 31, warp = tid >> 5;
    int bi = blockIdx.z, m0 = blockIdx.y * 128, n0 = blockIdx.x * 128;
    int wm = (warp >> 2) * 64, wn = (warp & 3) * 32;
    const char* srcs[4] = {
        (const char*)g_fdT_h + (size_t)(bi * LB + m0) * 256,
        (const char*)g_fdT_l + (size_t)(bi * LB + m0) * 256,
        (const char*)g_bdT_h + (size_t)(bi * LB + n0) * 256,
        (const char*)g_bdT_l + (size_t)(bi * LB + n0) * 256};
    float acc[4][4][4] = {};
    auto stage = [&](int ch, int s) {
        for (int u = tid; u < 2048; u += 256) {
            int t = u >> 9, idx = u & 511, r = idx >> 2, c4 = idx & 3;
            cp16(sb + (s * 4 + t) * TILEB + r * RS + c4 * 16,
                 srcs[t] + (size_t)r * 256 + ch * 64 + c4 * 16);
        }
    };
    stage(0, 0); CP_COMMIT;
    stage(1, 1); CP_COMMIT;
    for (int i = 0; i < 4; i++) {
        CP_WAIT1;
        __syncthreads();
        if (i + 2 < 4) stage(i + 2, (i + 2) % 3);
        CP_COMMIT;
        uint32_t base = sb + (i % 3) * 4 * TILEB;
        mma_chunk3(base, base + TILEB, base + 2 * TILEB, base + 3 * TILEB, wm, wn, lane, acc);
    }
    float* out = g_buf1 + ((size_t)bi << 20);
    #pragma unroll
    for (int mi = 0; mi < 4; mi++)
        #pragma unroll
        for (int nj = 0; nj < 4; nj++) {
            int grow = m0 + wm + mi * 16 + (lane >> 2);
            int gcol = n0 + wn + nj * 8 + (lane & 3) * 2;
            *(float2*)&out[(size_t)grow * LB + gcol] = make_float2(acc[mi][nj][0], acc[mi][nj][1]);
            *(float2*)&out[(size_t)(grow + 8) * LB + gcol] = make_float2(acc[mi][nj][2], acc[mi][nj][3]);
        }
}

// V[tap][lf][c] = attT[lf][:] . bp[tap][c][:]  (K=1024, 32 chunks)
__global__ __launch_bounds__(256) void k_mmaV() {
    extern __shared__ char smc[];
    uint32_t sb = s2u(smc);
    int tid = threadIdx.x, lane = tid & 31, warp = tid >> 5;
    int bi = blockIdx.z, tap = blockIdx.y, m0 = blockIdx.x * 128;
    int wm = (warp >> 2) * 64, wn = (warp & 3) * 32;
    const char* srcA = (const char*)g_attT + (size_t)(bi * LF + m0) * 2048;
    const char* srcB = (const char*)g_bp + (size_t)((bi * 16 + tap) * CC) * 2048;
    float acc[4][4][4] = {};
    const int NC = 32;
    auto stage = [&](int ch, int s) {
        for (int u = tid; u < 1024; u += 256) {
            int t = u >> 9, idx = u & 511, r = idx >> 2, c4 = idx & 3;
            cp16(sb + (s * 2 + t) * TILEB + r * RS + c4 * 16,
                 (t ? srcB : srcA) + (size_t)r * 2048 + ch * 64 + c4 * 16);
        }
    };
    stage(0, 0); CP_COMMIT;
    stage(1, 1); CP_COMMIT;
    for (int i = 0; i < NC; i++) {
        CP_WAIT1;
        __syncthreads();
        if (i + 2 < NC) stage(i + 2, (i + 2) % 3);
        CP_COMMIT;
        uint32_t base = sb + (i % 3) * 2 * TILEB;
        mma_chunk1(base, base + TILEB, wm, wn, lane, acc);
    }
    float* out = g_V + (size_t)(bi * 16 + tap) * LF * CC;
    #pragma unroll
    for (int mi = 0; mi < 4; mi++)
        #pragma unroll
        for (int nj = 0; nj < 4; nj++) {
            int glf = m0 + wm + mi * 16 + (lane >> 2);
            int gc = wn + nj * 8 + (lane & 3) * 2;
            *(float2*)&out[(size_t)glf * CC + gc] = make_float2(acc[mi][nj][0], acc[mi][nj][1]);
            *(float2*)&out[(size_t)(glf + 8) * CC + gc] = make_float2(acc[mi][nj][2], acc[mi][nj][3]);
        }
}

// conv3x3 implicit GEMM: M=128 pixels, N=128 co, K=1152 (36 chunks)
__global__ __launch_bounds__(256) void k_mmaConv(
    const __half* __restrict__ X, const __half* __restrict__ Wp,
    const float* __restrict__ bias, float* __restrict__ fout, int mode) {
    extern __shared__ char smc[];
    uint32_t sb = s2u(smc);
    int tid = threadIdx.x, lane = tid & 31, warp = tid >> 5;
    int bi = blockIdx.z, n0 = blockIdx.x * 128;
    int wm = (warp >> 2) * 64, wn = (warp & 3) * 32;
    const char* Xb = (const char*)X + (size_t)bi * 4096 * 256;
    const char* Wb = (const char*)Wp;
    float acc[4][4][4] = {};
    const int NC = 36;
    auto stage = [&](int ch, int s) {
        int tap = ch >> 2, ci0 = (ch & 3) * 32;
        int ky = tap / 3 - 1, kx = tap % 3 - 1;
        for (int u = tid; u < 1024; u += 256) {
            int t = u >> 9, idx = u & 511, r = idx >> 2, c4 = idx & 3;
            uint32_t dst = sb + (s * 2 + t) * TILEB + r * RS + c4 * 16;
            if (t) {
                cp16(dst, Wb + (size_t)r * 2304 + (tap * 128 + ci0) * 2 + c4 * 16);
            } else {
                int p = n0 + r;
                int sy = (p >> 6) + ky, sx = (p & 63) + kx;
                bool ok = (unsigned)sy < 64u && (unsigned)sx < 64u;
                int sp = ok ? sy * 64 + sx : 0;
                cp16z(dst, Xb + (size_t)sp * 256 + ci0 * 2 + c4 * 16, ok);
            }
        }
    };
    stage(0, 0); CP_COMMIT;
    stage(1, 1); CP_COMMIT;
    for (int i = 0; i < NC; i++) {
        CP_WAIT1;
        __syncthreads();
        if (i + 2 < NC) stage(i + 2, (i + 2) % 3);
        CP_COMMIT;
        uint32_t base = sb + (i % 3) * 2 * TILEB;
        mma_chunk1(base, base + TILEB, wm, wn, lane, acc);
    }
    if (mode == 0) {
        #pragma unroll
        for (int mi = 0; mi < 4; mi++)
            #pragma unroll
            for (int nj = 0; nj < 4; nj++) {
                int pr = wm + mi * 16 + (lane >> 2);
                int col = wn + nj * 8 + (lane & 3) * 2;
                float b0 = bias[col], b1 = bias[col + 1];
                float v0 = acc[mi][nj][0] + b0, v1 = acc[mi][nj][1] + b1;
                float v2 = acc[mi][nj][2] + b0, v3 = acc[mi][nj][3] + b1;
                v0 = v0 > 0.f ? v0 : expm1f(v0);
                v1 = v1 > 0.f ? v1 : expm1f(v1);
                v2 = v2 > 0.f ? v2 : expm1f(v2);
                v3 = v3 > 0.f ? v3 : expm1f(v3);
                __half2* o0 = (__half2*)&g_hT[((size_t)bi * 4096 + n0 + pr) * 128 + col];
                __half2* o1 = (__half2*)&g_hT[((size_t)bi * 4096 + n0 + pr + 8) * 128 + col];
                *o0 = __halves2half2(__float2half_rn(v0), __float2half_rn(v1));
                *o1 = __halves2half2(__float2half_rn(v2), __float2half_rn(v3));
            }
    } else {
        __syncthreads();
        float* sd = (float*)smc;
        #pragma unroll
        for (int mi = 0; mi < 4; mi++)
            #pragma unroll
            for (int nj = 0; nj < 4; nj++) {
                int pr = wm + mi * 16 + (lane >> 2);
                int col = wn + nj * 8 + (lane & 3) * 2;
                float b0 = bias[col], b1 = bias[col + 1];
                float v0 = acc[mi][nj][0] + b0, v1 = acc[mi][nj][1] + b1;
                float v2 = acc[mi][nj][2] + b0, v3 = acc[mi][nj][3] + b1;
                sd[pr * 129 + col] = v0 > 0.f ? v0 : expm1f(v0);
                sd[pr * 129 + col + 1] = v1 > 0.f ? v1 : expm1f(v1);
                sd[(pr + 8) * 129 + col] = v2 > 0.f ? v2 : expm1f(v2);
                sd[(pr + 8) * 129 + col + 1] = v3 > 0.f ? v3 : expm1f(v3);
            }
        __syncthreads();
        for (int u = tid; u < 16384; u += 256) {
            int pix = u & 127, co = u >> 7;
            fout[((size_t)bi * 128 + co) * 4096 + n0 + pix] = sd[pix * 129 + co];
        }
    }
}

// ---------------------------------------------------------------------------
extern "C" void kernel_launch(void* const* d_in, const int* in_sizes, int n_in,
                              void* d_out, int out_size) {
    const float* f  = (const float*)d_in[0];
    const float* b  = (const float*)d_in[1];
    const float* W1 = (const float*)d_in[2];
    const float* b1 = (const float*)d_in[3];
    const float* W2 = (const float*)d_in[4];
    const float* b2 = (const float*)d_in[5];
    float* out = (float*)d_out;

    cudaFuncSetAttribute(k_mmaG, cudaFuncAttributeMaxDynamicSharedMemorySize, 12 * TILEB);
    cudaFuncSetAttribute(k_mmaV, cudaFuncAttributeMaxDynamicSharedMemorySize, 6 * TILEB);
    cudaFuncSetAttribute(k_mmaConv, cudaFuncAttributeMaxDynamicSharedMemorySize, 66048);

    __half *yh, *hh, *w1p, *w2p;
    cudaGetSymbolAddress((void**)&yh, g_yT);
    cudaGetSymbolAddress((void**)&hh, g_hT);
    cudaGetSymbolAddress((void**)&w1p, g_W1p);
    cudaGetSymbolAddress((void**)&w2p, g_W2p);

    k_norm<<<BQ, 1024>>>(b);
    k_pack_down<<<dim3(32, 4, BQ), 256>>>(f, b);
    k_pack_bshift<<<(int)(((size_t)BQ * 16 * CC * LB + 255) / 256), 256>>>(b);
    k_packW<<<(CC * 1152 + 255) / 256, 256>>>(W1, W2);

    k_mmaG<<<dim3(8, 8, BQ), 256, 12 * TILEB>>>();
    k_ST<<<dim3(4096, BQ), 256>>>();
    k_fuse12T<<<dim3(4096, BQ), 256>>>();
    k_softmaxT<<<dim3(128, BQ), 256>>>();

    k_mmaV<<<dim3(8, 16, BQ), 256, 6 * TILEB>>>();
    k_comb_pack<<<(int)(((size_t)BQ * 4096 * CC + 255) / 256), 256>>>();

    k_mmaConv<<<dim3(32, 1, BQ), 256, 66048>>>(yh, w1p, b1, nullptr, 0);
    k_mmaConv<<<dim3(32, 1, BQ), 256, 66048>>>(hh, w2p, b2, out, 1);

    (void)in_sizes; (void)n_in; (void)out_size;
}